// round 2
// baseline (speedup 1.0000x reference)
#include <cuda_runtime.h>
#include <math.h>

#define EPS 1e-5f
constexpr int NN   = 8192;
constexpr int IND  = 343;
constexpr int HIDD = 1000;
constexpr int OUTD = 4;

// Scratch (allocation-free rule): xw = X@W1, h1 = relu(adj@xw + b1)
__device__ float g_xw[(size_t)NN * HIDD];
__device__ float g_h1[(size_t)NN * HIDD];

// ---------------------------------------------------------------------------
// Classic SGEMM: C[M,N] = A[M,K] @ B[K,N]  (+ optional bias+ReLU epilogue)
// BM=BN=128, BK=16, 256 threads, 8x8 per-thread microtile.
// ---------------------------------------------------------------------------
template<bool FUSE_BIAS_RELU>
__global__ __launch_bounds__(256)
void sgemm128x128(const float* __restrict__ A, const float* __restrict__ B,
                  const float* __restrict__ bias, float* __restrict__ C,
                  int M, int N, int K, int lda, int ldb, int ldc)
{
    constexpr int BM = 128, BN = 128, BK = 16;
    // As transposed [k][m], padded +4 so stores are ~2-way and LDS.128 stays aligned
    __shared__ float As[BK][BM + 4];
    __shared__ float Bs[BK][BN];

    const int tid = threadIdx.x;
    const int tx  = tid & 15;   // column group
    const int ty  = tid >> 4;   // row group
    const int m0  = blockIdx.y * BM;
    const int n0  = blockIdx.x * BN;

    float acc[8][8];
    #pragma unroll
    for (int i = 0; i < 8; i++)
        #pragma unroll
        for (int j = 0; j < 8; j++) acc[i][j] = 0.f;

    for (int k0 = 0; k0 < K; k0 += BK) {
        // Load A tile: 128x16, coalesced along K (16 floats = 64B per 16 threads)
        #pragma unroll
        for (int r = 0; r < 8; r++) {
            int idx = tid + r * 256;        // 0..2047
            int i = idx >> 4;               // m within tile
            int j = idx & 15;               // k within tile
            int gm = m0 + i, gk = k0 + j;
            float v = 0.f;
            if (gm < M && gk < K) v = A[(size_t)gm * lda + gk];
            As[j][i] = v;
        }
        // Load B tile: 16x128, fully coalesced along N
        #pragma unroll
        for (int r = 0; r < 8; r++) {
            int idx = tid + r * 256;
            int i = idx >> 7;               // k within tile
            int j = idx & 127;              // n within tile
            int gk = k0 + i, gn = n0 + j;
            float v = 0.f;
            if (gk < K && gn < N) v = B[(size_t)gk * ldb + gn];
            Bs[i][j] = v;
        }
        __syncthreads();

        #pragma unroll
        for (int kk = 0; kk < BK; kk++) {
            float a[8], b[8];
            #pragma unroll
            for (int i = 0; i < 8; i++) a[i] = As[kk][ty * 8 + i];
            #pragma unroll
            for (int j = 0; j < 8; j++) b[j] = Bs[kk][tx * 8 + j];
            #pragma unroll
            for (int i = 0; i < 8; i++)
                #pragma unroll
                for (int j = 0; j < 8; j++)
                    acc[i][j] = fmaf(a[i], b[j], acc[i][j]);
        }
        __syncthreads();
    }

    // Epilogue
    #pragma unroll
    for (int i = 0; i < 8; i++) {
        int gm = m0 + ty * 8 + i;
        if (gm >= M) continue;
        #pragma unroll
        for (int j = 0; j < 8; j++) {
            int gn = n0 + tx * 8 + j;
            if (gn >= N) continue;
            float v = acc[i][j];
            if (FUSE_BIAS_RELU) v = fmaxf(v + bias[gn], 0.f);
            C[(size_t)gm * ldc + gn] = v;
        }
    }
}

// ---------------------------------------------------------------------------
// LayerNorm(HID=1000) + head (1000 -> 4), one warp per row.
// blockDim = (32, 8): 8 rows per block.
// ---------------------------------------------------------------------------
__global__ __launch_bounds__(256)
void ln_head_kernel(const float* __restrict__ h,
                    const float* __restrict__ gamma,
                    const float* __restrict__ beta,
                    const float* __restrict__ Wm,
                    const float* __restrict__ bm,
                    float* __restrict__ out)
{
    const int row  = blockIdx.x * 8 + threadIdx.y;
    if (row >= NN) return;
    const int lane = threadIdx.x;
    const float* hr = h + (size_t)row * HIDD;

    // Cache this lane's elements (32 iters cover 1024 >= 1000)
    float v[32];
    float s = 0.f, ss = 0.f;
    #pragma unroll
    for (int i = 0; i < 32; i++) {
        int n = lane + 32 * i;
        float x = (n < HIDD) ? hr[n] : 0.f;
        v[i] = x;
        s  += x;
        ss += x * x;
    }
    // Warp reductions
    #pragma unroll
    for (int off = 16; off > 0; off >>= 1) {
        s  += __shfl_xor_sync(0xFFFFFFFF, s,  off);
        ss += __shfl_xor_sync(0xFFFFFFFF, ss, off);
    }
    const float mu   = s * (1.0f / HIDD);
    const float var  = ss * (1.0f / HIDD) - mu * mu;
    const float rinv = rsqrtf(var + EPS);

    float acc[OUTD] = {0.f, 0.f, 0.f, 0.f};
    #pragma unroll
    for (int i = 0; i < 32; i++) {
        int n = lane + 32 * i;
        if (n < HIDD) {
            float xn = (v[i] - mu) * rinv * gamma[n] + beta[n];
            #pragma unroll
            for (int o = 0; o < OUTD; o++)
                acc[o] = fmaf(xn, Wm[n * OUTD + o], acc[o]);
        }
    }
    #pragma unroll
    for (int o = 0; o < OUTD; o++) {
        #pragma unroll
        for (int off = 16; off > 0; off >>= 1)
            acc[o] += __shfl_xor_sync(0xFFFFFFFF, acc[o], off);
    }
    if (lane == 0) {
        #pragma unroll
        for (int o = 0; o < OUTD; o++)
            out[(size_t)row * OUTD + o] = acc[o] + bm[o];
    }
}

// ---------------------------------------------------------------------------
// Launch: xw = X@W1 ; h1 = relu(adj@xw + b1) ; out = LN(h1)@Wm + bm
// ---------------------------------------------------------------------------
extern "C" void kernel_launch(void* const* d_in, const int* in_sizes, int n_in,
                              void* d_out, int out_size)
{
    const float* adj   = (const float*)d_in[0];  // [8192, 8192]
    const float* feat  = (const float*)d_in[1];  // [8192, 343]
    const float* W1    = (const float*)d_in[2];  // [343, 1000]
    const float* b1    = (const float*)d_in[3];  // [1000]
    const float* gamma = (const float*)d_in[4];  // [1000]
    const float* beta  = (const float*)d_in[5];  // [1000]
    const float* Wm    = (const float*)d_in[6];  // [1000, 4]
    const float* bm    = (const float*)d_in[7];  // [4]
    float* out = (float*)d_out;                  // [8192, 4]

    float *xw, *h1;
    cudaGetSymbolAddress((void**)&xw, g_xw);
    cudaGetSymbolAddress((void**)&h1, g_h1);

    // GEMM1: [8192,343] @ [343,1000] -> xw
    {
        dim3 grid((HIDD + 127) / 128, (NN + 127) / 128);
        sgemm128x128<false><<<grid, 256>>>(feat, W1, nullptr, xw,
                                           NN, HIDD, IND, IND, HIDD, HIDD);
    }
    // GEMM2: relu([8192,8192] @ xw + b1) -> h1
    {
        dim3 grid((HIDD + 127) / 128, (NN + 127) / 128);
        sgemm128x128<true><<<grid, 256>>>(adj, xw, b1, h1,
                                          NN, HIDD, NN, NN, HIDD, HIDD);
    }
    // LayerNorm + head
    {
        dim3 block(32, 8);
        ln_head_kernel<<<NN / 8, block>>>(h1, gamma, beta, Wm, bm, out);
    }
}

// round 3
// speedup vs baseline: 3.6408x; 3.6408x over previous
#include <cuda_runtime.h>
#include <math.h>
#include <stdint.h>

#define EPS 1e-5f
constexpr int NN   = 8192;
constexpr int IND  = 343;
constexpr int HIDD = 1000;
constexpr int OUTD = 4;

__device__ float g_xw[(size_t)NN * HIDD];
__device__ float g_h1[(size_t)NN * HIDD];

// ---------------------------------------------------------------------------
// TF32 tensor-core GEMM: C[M,N] = A[M,K] @ B[K,N] (+ optional bias+ReLU)
// BM=BN=128, BK=32, 256 threads (8 warps, 2x4 warp grid, 64x32 warp tile)
// cp.async double-buffered smem. mma.sync.m16n8k8.tf32.
// ---------------------------------------------------------------------------
constexpr int BM = 128, BN = 128, BK = 32;
constexpr int LDAS = 36;   // A smem stride (floats): conflict-free frag loads
constexpr int LDBS = 136;  // B smem stride (floats): conflict-free frag loads
constexpr int A_SZ = BM * LDAS;        // 4608 floats
constexpr int B_SZ = BK * LDBS;        // 4352 floats
constexpr int STAGE = A_SZ + B_SZ;     // 8960 floats
constexpr int SMEM_BYTES = 2 * STAGE * 4;  // 71680 B

__device__ __forceinline__ void cp_async16(uint32_t dst, const void* src, int bytes) {
    asm volatile("cp.async.cg.shared.global [%0], [%1], 16, %2;\n"
                 :: "r"(dst), "l"(src), "r"(bytes));
}
__device__ __forceinline__ void cp_async4(uint32_t dst, const void* src, int bytes) {
    asm volatile("cp.async.ca.shared.global [%0], [%1], 4, %2;\n"
                 :: "r"(dst), "l"(src), "r"(bytes));
}
__device__ __forceinline__ void cp_commit() {
    asm volatile("cp.async.commit_group;\n" ::: "memory");
}
__device__ __forceinline__ uint32_t f2tf32(float v) {
    uint32_t r;
    asm("cvt.rna.tf32.f32 %0, %1;" : "=r"(r) : "f"(v));
    return r;
}
__device__ __forceinline__ void mma_tf32(float* d, const uint32_t* a, const uint32_t* b) {
    asm volatile(
        "mma.sync.aligned.m16n8k8.row.col.f32.tf32.tf32.f32 "
        "{%0,%1,%2,%3}, {%4,%5,%6,%7}, {%8,%9}, {%0,%1,%2,%3};"
        : "+f"(d[0]), "+f"(d[1]), "+f"(d[2]), "+f"(d[3])
        : "r"(a[0]), "r"(a[1]), "r"(a[2]), "r"(a[3]), "r"(b[0]), "r"(b[1]));
}

template<bool A16, bool FUSE_BIAS_RELU>
__global__ __launch_bounds__(256, 1)
void tf32_gemm(const float* __restrict__ A, const float* __restrict__ B,
               const float* __restrict__ bias, float* __restrict__ C,
               int M, int N, int K, int lda, int ldb, int ldc)
{
    extern __shared__ float sm[];
    const int tid  = threadIdx.x;
    const int lane = tid & 31;
    const int wid  = tid >> 5;
    const int wm0  = (wid & 1) * 64;   // warp tile row origin
    const int wn0  = (wid >> 1) * 32;  // warp tile col origin
    const int m0   = blockIdx.y * BM;
    const int n0   = blockIdx.x * BN;
    const uint32_t smbase = (uint32_t)__cvta_generic_to_shared(sm);

    float acc[4][4][4];
    #pragma unroll
    for (int i = 0; i < 4; i++)
        #pragma unroll
        for (int j = 0; j < 4; j++)
            #pragma unroll
            for (int q = 0; q < 4; q++) acc[i][j][q] = 0.f;

    auto loadA = [&](int kt, int s) {
        const int k0 = kt * BK;
        if (A16) {
            // 128x32 tile, 16B chunks: 1024 chunks, 4 per thread
            #pragma unroll
            for (int t = 0; t < 4; t++) {
                int id = tid + t * 256;
                int m = id >> 3, c = id & 7;
                int gk = k0 + c * 4;
                int bytes = (K - gk) * 4;
                bytes = bytes < 0 ? 0 : (bytes > 16 ? 16 : bytes);
                const float* src = bytes ? (A + (size_t)(m0 + m) * lda + gk) : A;
                cp_async16(smbase + (uint32_t)(s * STAGE + m * LDAS + c * 4) * 4, src, bytes);
            }
        } else {
            // 4B path (unaligned global rows)
            #pragma unroll
            for (int t = 0; t < 16; t++) {
                int id = tid + t * 256;
                int m = id >> 5, c = id & 31;
                int gk = k0 + c;
                int bytes = (gk < K) ? 4 : 0;
                const float* src = bytes ? (A + (size_t)(m0 + m) * lda + gk) : A;
                cp_async4(smbase + (uint32_t)(s * STAGE + m * LDAS + c) * 4, src, bytes);
            }
        }
    };
    auto loadB = [&](int kt, int s) {
        const int k0 = kt * BK;
        #pragma unroll
        for (int t = 0; t < 4; t++) {
            int id = tid + t * 256;
            int k = id >> 5, c = id & 31;
            int gk = k0 + k;
            int gn = n0 + c * 4;
            int bytes = 0;
            if (gk < K) {
                bytes = (N - gn) * 4;
                bytes = bytes < 0 ? 0 : (bytes > 16 ? 16 : bytes);
            }
            const float* src = bytes ? (B + (size_t)gk * ldb + gn) : B;
            cp_async16(smbase + (uint32_t)(s * STAGE + A_SZ + k * LDBS + c * 4) * 4, src, bytes);
        }
    };

    const int KT = (K + BK - 1) / BK;
    const int r = lane >> 2, c4 = lane & 3;

    loadA(0, 0); loadB(0, 0); cp_commit();

    for (int kt = 0; kt < KT; kt++) {
        if (kt + 1 < KT) {
            loadA(kt + 1, (kt + 1) & 1);
            loadB(kt + 1, (kt + 1) & 1);
            cp_commit();
            asm volatile("cp.async.wait_group 1;\n" ::: "memory");
        } else {
            asm volatile("cp.async.wait_group 0;\n" ::: "memory");
        }
        __syncthreads();

        const float* As  = sm + (kt & 1) * STAGE;
        const float* Bsm = As + A_SZ;
        #pragma unroll
        for (int kk4 = 0; kk4 < 4; kk4++) {
            const int kk = kk4 * 8;
            uint32_t a[4][4], b[4][2];
            #pragma unroll
            for (int mi = 0; mi < 4; mi++) {
                int base = (wm0 + mi * 16 + r) * LDAS + kk + c4;
                a[mi][0] = f2tf32(As[base]);
                a[mi][1] = f2tf32(As[base + 8 * LDAS]);
                a[mi][2] = f2tf32(As[base + 4]);
                a[mi][3] = f2tf32(As[base + 8 * LDAS + 4]);
            }
            #pragma unroll
            for (int ni = 0; ni < 4; ni++) {
                int bb = (kk + c4) * LDBS + wn0 + ni * 8 + r;
                b[ni][0] = f2tf32(Bsm[bb]);
                b[ni][1] = f2tf32(Bsm[bb + 4 * LDBS]);
            }
            #pragma unroll
            for (int mi = 0; mi < 4; mi++)
                #pragma unroll
                for (int ni = 0; ni < 4; ni++)
                    mma_tf32(acc[mi][ni], a[mi], b[ni]);
        }
        __syncthreads();
    }

    // Epilogue (M is a multiple of 128 here, so no row guards)
    #pragma unroll
    for (int mi = 0; mi < 4; mi++) {
        #pragma unroll
        for (int ni = 0; ni < 4; ni++) {
            int row0 = m0 + wm0 + mi * 16 + r;
            int col0 = n0 + wn0 + ni * 8 + c4 * 2;
            #pragma unroll
            for (int h = 0; h < 2; h++) {     // h=0: rows r, h=1: rows r+8
                int row = row0 + h * 8;
                #pragma unroll
                for (int q = 0; q < 2; q++) {
                    int col = col0 + q;
                    if (col < N) {
                        float v = acc[mi][ni][h * 2 + q];
                        if (FUSE_BIAS_RELU) v = fmaxf(v + bias[col], 0.f);
                        C[(size_t)row * ldc + col] = v;
                    }
                }
            }
        }
    }
}

// ---------------------------------------------------------------------------
// LayerNorm(1000) + head (1000 -> 4), one warp per row.
// ---------------------------------------------------------------------------
__global__ __launch_bounds__(256)
void ln_head_kernel(const float* __restrict__ h,
                    const float* __restrict__ gamma,
                    const float* __restrict__ beta,
                    const float* __restrict__ Wm,
                    const float* __restrict__ bm,
                    float* __restrict__ out)
{
    const int row  = blockIdx.x * 8 + threadIdx.y;
    if (row >= NN) return;
    const int lane = threadIdx.x;
    const float* hr = h + (size_t)row * HIDD;

    float v[32];
    float s = 0.f, ss = 0.f;
    #pragma unroll
    for (int i = 0; i < 32; i++) {
        int n = lane + 32 * i;
        float x = (n < HIDD) ? hr[n] : 0.f;
        v[i] = x;
        s  += x;
        ss += x * x;
    }
    #pragma unroll
    for (int off = 16; off > 0; off >>= 1) {
        s  += __shfl_xor_sync(0xFFFFFFFF, s,  off);
        ss += __shfl_xor_sync(0xFFFFFFFF, ss, off);
    }
    const float mu   = s * (1.0f / HIDD);
    const float var  = ss * (1.0f / HIDD) - mu * mu;
    const float rinv = rsqrtf(var + EPS);

    float acc[OUTD] = {0.f, 0.f, 0.f, 0.f};
    #pragma unroll
    for (int i = 0; i < 32; i++) {
        int n = lane + 32 * i;
        if (n < HIDD) {
            float xn = (v[i] - mu) * rinv * gamma[n] + beta[n];
            #pragma unroll
            for (int o = 0; o < OUTD; o++)
                acc[o] = fmaf(xn, Wm[n * OUTD + o], acc[o]);
        }
    }
    #pragma unroll
    for (int o = 0; o < OUTD; o++) {
        #pragma unroll
        for (int off = 16; off > 0; off >>= 1)
            acc[o] += __shfl_xor_sync(0xFFFFFFFF, acc[o], off);
    }
    if (lane == 0) {
        #pragma unroll
        for (int o = 0; o < OUTD; o++)
            out[(size_t)row * OUTD + o] = acc[o] + bm[o];
    }
}

// ---------------------------------------------------------------------------
extern "C" void kernel_launch(void* const* d_in, const int* in_sizes, int n_in,
                              void* d_out, int out_size)
{
    const float* adj   = (const float*)d_in[0];
    const float* feat  = (const float*)d_in[1];
    const float* W1    = (const float*)d_in[2];
    const float* b1    = (const float*)d_in[3];
    const float* gamma = (const float*)d_in[4];
    const float* beta  = (const float*)d_in[5];
    const float* Wm    = (const float*)d_in[6];
    const float* bm    = (const float*)d_in[7];
    float* out = (float*)d_out;

    float *xw, *h1;
    cudaGetSymbolAddress((void**)&xw, g_xw);
    cudaGetSymbolAddress((void**)&h1, g_h1);

    cudaFuncSetAttribute(tf32_gemm<false, false>,
                         cudaFuncAttributeMaxDynamicSharedMemorySize, SMEM_BYTES);
    cudaFuncSetAttribute(tf32_gemm<true, true>,
                         cudaFuncAttributeMaxDynamicSharedMemorySize, SMEM_BYTES);

    dim3 grid((HIDD + BN - 1) / BN, NN / BM);

    // GEMM1: xw = feat @ W1   (A rows not 16B aligned -> 4B cp.async path)
    tf32_gemm<false, false><<<grid, 256, SMEM_BYTES>>>(
        feat, W1, nullptr, xw, NN, HIDD, IND, IND, HIDD, HIDD);

    // GEMM2: h1 = relu(adj @ xw + b1)
    tf32_gemm<true, true><<<grid, 256, SMEM_BYTES>>>(
        adj, xw, b1, h1, NN, HIDD, NN, NN, HIDD, HIDD);

    // LayerNorm + head
    dim3 block(32, 8);
    ln_head_kernel<<<NN / 8, block>>>(h1, gamma, beta, Wm, bm, out);
}

// round 6
// speedup vs baseline: 4.2726x; 1.1735x over previous
#include <cuda_runtime.h>
#include <math.h>
#include <stdint.h>

#define EPS 1e-5f
constexpr int NN   = 8192;
constexpr int IND  = 343;
constexpr int HIDD = 1000;
constexpr int HPAD = 1024;
constexpr int OUTD = 4;

// Scratch (allocation-free rule)
__device__ float g_xw[(size_t)NN * HPAD];   // X@W1 (raw fp32, padded cols zero)
__device__ float g_xwT[(size_t)HPAD * NN];  // transposed, RNA-rounded, k-permuted
__device__ float g_h1[(size_t)NN * HPAD];   // relu(adj@xw + b1)
__device__ float g_b1p[HPAD];

// ---------------------------------------------------------------------------
// helpers (base PTX only — sm_100 target has no tcgen05)
// ---------------------------------------------------------------------------
__device__ __forceinline__ uint32_t f2tf32(float v) {
    uint32_t r; asm("cvt.rna.tf32.f32 %0, %1;" : "=r"(r) : "f"(v)); return r;
}
__device__ __forceinline__ float rna_f(float v) { return __uint_as_float(f2tf32(v)); }

__device__ __forceinline__ void cp_async16(uint32_t dst, const void* src) {
    asm volatile("cp.async.cg.shared.global [%0], [%1], 16;\n" :: "r"(dst), "l"(src));
}
__device__ __forceinline__ void cp_async16b(uint32_t dst, const void* src, int bytes) {
    asm volatile("cp.async.cg.shared.global [%0], [%1], 16, %2;\n" :: "r"(dst), "l"(src), "r"(bytes));
}
__device__ __forceinline__ void cp_async4(uint32_t dst, const void* src, int bytes) {
    asm volatile("cp.async.ca.shared.global [%0], [%1], 4, %2;\n" :: "r"(dst), "l"(src), "r"(bytes));
}
__device__ __forceinline__ void cp_commit() {
    asm volatile("cp.async.commit_group;\n" ::: "memory");
}
#define CP_WAIT(n) asm volatile("cp.async.wait_group %0;\n" :: "n"(n) : "memory")

__device__ __forceinline__ void mma_tf32(float* d, const uint32_t* a, const uint32_t* b) {
    asm volatile(
        "mma.sync.aligned.m16n8k8.row.col.f32.tf32.tf32.f32 "
        "{%0,%1,%2,%3}, {%4,%5,%6,%7}, {%8,%9}, {%0,%1,%2,%3};"
        : "+f"(d[0]), "+f"(d[1]), "+f"(d[2]), "+f"(d[3])
        : "r"(a[0]), "r"(a[1]), "r"(a[2]), "r"(a[3]), "r"(b[0]), "r"(b[1]));
}

// ---------------------------------------------------------------------------
// GEMM2: h1 = relu(adj @ xw + b1)   [M=8192, N=1024, K=8192]
// A = adj (raw fp32, RNA'd in fill path), B = xwT [n][k] pre-rounded+permuted.
// CTA 128m x 256n, BK=32, 8 warps (2x4) of 64x64 tiles (mi=4, ni=8).
// A: LDG.128->cvt->STS.128 (prefetch dist 1). B: 3-stage cp.async (dist 2).
// ---------------------------------------------------------------------------
constexpr int LDA_S = 36;                      // floats per A smem row
constexpr int LDB_S = 40;                      // floats per B smem row
constexpr int A_STG = 128 * LDA_S;             // 4608
constexpr int B_STG = 256 * LDB_S;             // 10240
constexpr int B_BASE = 2 * A_STG;              // floats
constexpr int G2_SMEM = (2 * A_STG + 3 * B_STG) * 4;   // 159744 B
constexpr int KT2 = NN / 32;                   // 256

__global__ __launch_bounds__(256, 1)
void gemm2_mma(const float* __restrict__ adj,
               const float* __restrict__ xwT,
               const float* __restrict__ bias,
               float* __restrict__ C)
{
    extern __shared__ float smf[];
    const uint32_t smb = (uint32_t)__cvta_generic_to_shared(smf);
    const int tid  = threadIdx.x;
    const int lane = tid & 31;
    const int wid  = tid >> 5;
    const int wm   = (wid & 1) * 64;
    const int wn   = (wid >> 1) * 64;
    const int r    = lane >> 2;
    const int c4   = lane & 3;
    const int m0   = blockIdx.y * 128;
    const int n0   = blockIdx.x * 256;

    const float* Abase = adj + (size_t)m0 * NN;
    const float* Bbase = xwT + (size_t)n0 * NN;

    float acc[4][8][4];
    #pragma unroll
    for (int i = 0; i < 4; i++)
        #pragma unroll
        for (int j = 0; j < 8; j++)
            #pragma unroll
            for (int q = 0; q < 4; q++) acc[i][j][q] = 0.f;

    float4 buf[4];

    auto ldgA = [&](int kt) {
        #pragma unroll
        for (int c = 0; c < 4; c++) {
            int chunk = tid + c * 256;         // 0..1023
            int row = chunk >> 3, pos = chunk & 7;
            buf[c] = *(const float4*)(Abase + (size_t)row * NN + kt * 32 + pos * 4);
        }
    };
    auto stsA = [&](int s) {
        float* As = smf + s * A_STG;
        #pragma unroll
        for (int c = 0; c < 4; c++) {
            int chunk = tid + c * 256;
            int row = chunk >> 3, pos = chunk & 7;
            float4 v = buf[c];
            v.x = rna_f(v.x); v.y = rna_f(v.y); v.z = rna_f(v.z); v.w = rna_f(v.w);
            *(float4*)(As + row * LDA_S + pos * 4) = v;
        }
    };
    auto cpB = [&](int kt, int s) {
        uint32_t bs = smb + (uint32_t)(B_BASE + s * B_STG) * 4;
        const float* Bb = Bbase + kt * 32;
        #pragma unroll
        for (int c = 0; c < 8; c++) {
            int chunk = tid + c * 256;         // 0..2047
            int row = chunk >> 3, pos = chunk & 7;
            cp_async16(bs + (uint32_t)(row * LDB_S + pos * 4) * 4,
                       Bb + (size_t)row * NN + pos * 4);
        }
        cp_commit();
    };

    // prologue
    ldgA(0);
    cpB(0, 0);
    cpB(1, 1);

    for (int kt = 0; kt < KT2; kt++) {
        stsA(kt & 1);
        if (kt + 1 < KT2) { CP_WAIT(1); } else { CP_WAIT(0); }
        __syncthreads();
        if (kt + 1 < KT2) ldgA(kt + 1);
        if (kt + 2 < KT2) cpB(kt + 2, (kt + 2) % 3);

        const uint32_t* As = (const uint32_t*)(smf + (kt & 1) * A_STG);
        const uint32_t* Bs = (const uint32_t*)(smf + B_BASE + (kt % 3) * B_STG);
        const float*    Bf = (const float*)Bs;

        #pragma unroll
        for (int g = 0; g < 4; g++) {
            const int kk = g * 8;
            uint32_t a[4][4], b[8][2];
            #pragma unroll
            for (int mi = 0; mi < 4; mi++) {
                int base = (wm + mi * 16 + r) * LDA_S + kk + c4;
                a[mi][0] = As[base];
                a[mi][1] = As[base + 8 * LDA_S];
                a[mi][2] = As[base + 4];
                a[mi][3] = As[base + 8 * LDA_S + 4];
            }
            #pragma unroll
            for (int ni = 0; ni < 8; ni++) {
                // permuted rows: (k=c4, k=c4+4) adjacent -> one LDS.64
                float2 v = *(const float2*)(Bf + (wn + ni * 8 + r) * LDB_S + kk + 2 * c4);
                b[ni][0] = __float_as_uint(v.x);
                b[ni][1] = __float_as_uint(v.y);
            }
            #pragma unroll
            for (int mi = 0; mi < 4; mi++)
                #pragma unroll
                for (int ni = 0; ni < 8; ni++)
                    mma_tf32(acc[mi][ni], a[mi], b[ni]);
        }
        __syncthreads();
    }

    // epilogue: bias + relu, store [m][HPAD]
    #pragma unroll
    for (int mi = 0; mi < 4; mi++) {
        #pragma unroll
        for (int h = 0; h < 2; h++) {
            int row = m0 + wm + mi * 16 + r + h * 8;
            float* dst = C + (size_t)row * HPAD + n0 + wn;
            #pragma unroll
            for (int ni = 0; ni < 8; ni++) {
                int col = ni * 8 + c4 * 2;
                float2 v;
                v.x = fmaxf(acc[mi][ni][h * 2 + 0] + bias[n0 + wn + col],     0.f);
                v.y = fmaxf(acc[mi][ni][h * 2 + 1] + bias[n0 + wn + col + 1], 0.f);
                *(float2*)(dst + col) = v;
            }
        }
    }
}

// ---------------------------------------------------------------------------
// GEMM1 (R3, proven): xw = feat @ W1  [tf32 HMMA, cvt in-loop — K=343, small]
// ---------------------------------------------------------------------------
constexpr int BM = 128, BN = 128, BK = 32;
constexpr int LDAS = 36, LDBS = 136;
constexpr int A_SZ = BM * LDAS, B_SZ = BK * LDBS;
constexpr int STAGE = A_SZ + B_SZ;
constexpr int G1_SMEM = 2 * STAGE * 4;

__global__ __launch_bounds__(256, 1)
void gemm1_hmma(const float* __restrict__ A, const float* __restrict__ B,
                float* __restrict__ C, int M, int N, int K, int lda, int ldb, int ldc)
{
    extern __shared__ float sm[];
    const int tid = threadIdx.x, lane = tid & 31, wid = tid >> 5;
    const int wm0 = (wid & 1) * 64, wn0 = (wid >> 1) * 32;
    const int m0 = blockIdx.y * BM, n0 = blockIdx.x * BN;
    const uint32_t smbase = (uint32_t)__cvta_generic_to_shared(sm);

    float acc[4][4][4];
    #pragma unroll
    for (int i = 0; i < 4; i++)
        #pragma unroll
        for (int j = 0; j < 4; j++)
            #pragma unroll
            for (int q = 0; q < 4; q++) acc[i][j][q] = 0.f;

    auto loadA = [&](int kt, int s) {
        const int k0 = kt * BK;
        #pragma unroll
        for (int t = 0; t < 16; t++) {
            int id = tid + t * 256;
            int m = id >> 5, c = id & 31;
            int gk = k0 + c;
            int bytes = (gk < K) ? 4 : 0;
            const float* src = bytes ? (A + (size_t)(m0 + m) * lda + gk) : A;
            cp_async4(smbase + (uint32_t)(s * STAGE + m * LDAS + c) * 4, src, bytes);
        }
    };
    auto loadB = [&](int kt, int s) {
        const int k0 = kt * BK;
        #pragma unroll
        for (int t = 0; t < 4; t++) {
            int id = tid + t * 256;
            int k = id >> 5, c = id & 31;
            int gk = k0 + k, gn = n0 + c * 4;
            int bytes = 0;
            if (gk < K) { bytes = (N - gn) * 4; bytes = bytes < 0 ? 0 : (bytes > 16 ? 16 : bytes); }
            const float* src = bytes ? (B + (size_t)gk * ldb + gn) : B;
            cp_async16b(smbase + (uint32_t)(s * STAGE + A_SZ + k * LDBS + c * 4) * 4, src, bytes);
        }
    };

    const int KT = (K + BK - 1) / BK;
    const int r = lane >> 2, c4 = lane & 3;
    loadA(0, 0); loadB(0, 0); cp_commit();

    for (int kt = 0; kt < KT; kt++) {
        if (kt + 1 < KT) {
            loadA(kt + 1, (kt + 1) & 1);
            loadB(kt + 1, (kt + 1) & 1);
            cp_commit();
            CP_WAIT(1);
        } else {
            CP_WAIT(0);
        }
        __syncthreads();
        const float* As  = sm + (kt & 1) * STAGE;
        const float* Bsm = As + A_SZ;
        #pragma unroll
        for (int kk4 = 0; kk4 < 4; kk4++) {
            const int kk = kk4 * 8;
            uint32_t a[4][4], b[4][2];
            #pragma unroll
            for (int mi = 0; mi < 4; mi++) {
                int base = (wm0 + mi * 16 + r) * LDAS + kk + c4;
                a[mi][0] = f2tf32(As[base]);
                a[mi][1] = f2tf32(As[base + 8 * LDAS]);
                a[mi][2] = f2tf32(As[base + 4]);
                a[mi][3] = f2tf32(As[base + 8 * LDAS + 4]);
            }
            #pragma unroll
            for (int ni = 0; ni < 4; ni++) {
                int bb = (kk + c4) * LDBS + wn0 + ni * 8 + r;
                b[ni][0] = f2tf32(Bsm[bb]);
                b[ni][1] = f2tf32(Bsm[bb + 4 * LDBS]);
            }
            #pragma unroll
            for (int mi = 0; mi < 4; mi++)
                #pragma unroll
                for (int ni = 0; ni < 4; ni++)
                    mma_tf32(acc[mi][ni], a[mi], b[ni]);
        }
        __syncthreads();
    }

    #pragma unroll
    for (int mi = 0; mi < 4; mi++)
        #pragma unroll
        for (int ni = 0; ni < 4; ni++) {
            int row0 = m0 + wm0 + mi * 16 + r;
            int col0 = n0 + wn0 + ni * 8 + c4 * 2;
            #pragma unroll
            for (int h = 0; h < 2; h++) {
                int row = row0 + h * 8;
                #pragma unroll
                for (int q = 0; q < 2; q++) {
                    int col = col0 + q;
                    if (col < N) C[(size_t)row * ldc + col] = acc[mi][ni][h * 2 + q];
                }
            }
        }
}

// ---------------------------------------------------------------------------
// transpose + RNA round + k-permute: xw[8192][1024] -> xwT[1024][8192]
// k-permute within each 8-group: o -> (o<4 ? 2o : 2(o-4)+1)
// ---------------------------------------------------------------------------
__global__ void transpose_rna_perm(const float* __restrict__ in,
                                   float* __restrict__ out)
{
    __shared__ float t[32][33];
    int x  = blockIdx.x * 32 + threadIdx.x;   // n (col in `in`)
    int y0 = blockIdx.y * 32;                 // k base
    #pragma unroll
    for (int j = threadIdx.y; j < 32; j += 8)
        t[j][threadIdx.x] = in[(size_t)(y0 + j) * HPAD + x];
    __syncthreads();
    int k  = y0 + threadIdx.x;                // k (col in `out`)
    int o  = k & 7;
    int kp = (k & ~7) | ((o < 4) ? (2 * o) : (2 * (o - 4) + 1));
    int n0 = blockIdx.x * 32;
    #pragma unroll
    for (int j = threadIdx.y; j < 32; j += 8)
        out[(size_t)(n0 + j) * NN + kp] = rna_f(t[threadIdx.x][j]);
}

__global__ void pad_bias_kernel(const float* __restrict__ b1, float* __restrict__ b1p) {
    int i = threadIdx.x;
    b1p[i] = (i < HIDD) ? b1[i] : 0.f;
}

// ---------------------------------------------------------------------------
// LayerNorm(1000) + head, one warp per row.
// ---------------------------------------------------------------------------
__global__ __launch_bounds__(256)
void ln_head_kernel(const float* __restrict__ h,
                    const float* __restrict__ gamma,
                    const float* __restrict__ beta,
                    const float* __restrict__ Wm,
                    const float* __restrict__ bm,
                    float* __restrict__ out)
{
    const int row  = blockIdx.x * 8 + threadIdx.y;
    if (row >= NN) return;
    const int lane = threadIdx.x;
    const float* hr = h + (size_t)row * HPAD;

    float v[32];
    float s = 0.f, ss = 0.f;
    #pragma unroll
    for (int i = 0; i < 32; i++) {
        int n = lane + 32 * i;
        float x = (n < HIDD) ? hr[n] : 0.f;
        v[i] = x; s += x; ss += x * x;
    }
    #pragma unroll
    for (int off = 16; off > 0; off >>= 1) {
        s  += __shfl_xor_sync(0xFFFFFFFF, s,  off);
        ss += __shfl_xor_sync(0xFFFFFFFF, ss, off);
    }
    const float mu   = s * (1.0f / HIDD);
    const float var  = ss * (1.0f / HIDD) - mu * mu;
    const float rinv = rsqrtf(var + EPS);

    float acc[OUTD] = {0.f, 0.f, 0.f, 0.f};
    #pragma unroll
    for (int i = 0; i < 32; i++) {
        int n = lane + 32 * i;
        if (n < HIDD) {
            float xn = (v[i] - mu) * rinv * gamma[n] + beta[n];
            #pragma unroll
            for (int o = 0; o < OUTD; o++)
                acc[o] = fmaf(xn, Wm[n * OUTD + o], acc[o]);
        }
    }
    #pragma unroll
    for (int o = 0; o < OUTD; o++) {
        #pragma unroll
        for (int off = 16; off > 0; off >>= 1)
            acc[o] += __shfl_xor_sync(0xFFFFFFFF, acc[o], off);
    }
    if (lane == 0) {
        #pragma unroll
        for (int o = 0; o < OUTD; o++)
            out[(size_t)row * OUTD + o] = acc[o] + bm[o];
    }
}

// ---------------------------------------------------------------------------
extern "C" void kernel_launch(void* const* d_in, const int* in_sizes, int n_in,
                              void* d_out, int out_size)
{
    const float* adj   = (const float*)d_in[0];
    const float* feat  = (const float*)d_in[1];
    const float* W1    = (const float*)d_in[2];
    const float* b1    = (const float*)d_in[3];
    const float* gamma = (const float*)d_in[4];
    const float* beta  = (const float*)d_in[5];
    const float* Wm    = (const float*)d_in[6];
    const float* bm    = (const float*)d_in[7];
    float* out = (float*)d_out;

    float *xw, *xwT, *h1, *b1p;
    cudaGetSymbolAddress((void**)&xw,  g_xw);
    cudaGetSymbolAddress((void**)&xwT, g_xwT);
    cudaGetSymbolAddress((void**)&h1,  g_h1);
    cudaGetSymbolAddress((void**)&b1p, g_b1p);

    cudaFuncSetAttribute(gemm1_hmma, cudaFuncAttributeMaxDynamicSharedMemorySize, G1_SMEM);
    cudaFuncSetAttribute(gemm2_mma,  cudaFuncAttributeMaxDynamicSharedMemorySize, G2_SMEM);

    cudaMemsetAsync(xw, 0, (size_t)NN * HPAD * sizeof(float));
    pad_bias_kernel<<<1, HPAD>>>(b1, b1p);

    // GEMM1: xw = feat @ W1
    {
        dim3 grid((HIDD + BN - 1) / BN, NN / BM);
        gemm1_hmma<<<grid, 256, G1_SMEM>>>(feat, W1, xw, NN, HIDD, IND, IND, HIDD, HPAD);
    }

    // xwT = RNA(xw)^T with k-permute
    {
        dim3 block(32, 8), grid(HPAD / 32, NN / 32);
        transpose_rna_perm<<<grid, block>>>(xw, xwT);
    }

    // GEMM2: h1 = relu(adj @ xw + b1)
    {
        dim3 grid(HPAD / 256, NN / 128);   // x-fastest: 4 n-tiles share each A stripe
        gemm2_mma<<<grid, 256, G2_SMEM>>>(adj, xwT, b1p, h1);
    }

    // LayerNorm + head
    {
        dim3 block(32, 8);
        ln_head_kernel<<<NN / 8, block>>>(h1, gamma, beta, Wm, bm, out);
    }
}

// round 7
// speedup vs baseline: 4.2895x; 1.0040x over previous
#include <cuda_runtime.h>
#include <math.h>
#include <stdint.h>

#define EPS 1e-5f
constexpr int NN   = 8192;
constexpr int IND  = 343;
constexpr int HIDD = 1000;
constexpr int HPAD = 1024;
constexpr int OUTD = 4;

// Scratch (allocation-free rule)
__device__ float g_xw[(size_t)NN * HPAD];   // X@W1 (raw fp32, padded cols zero)
__device__ float g_xwT[(size_t)HPAD * NN];  // transposed, RNA-rounded, k-permuted
__device__ float g_h1[(size_t)NN * HPAD];   // relu(adj@xw + b1)
__device__ float g_b1p[HPAD];

// ---------------------------------------------------------------------------
// helpers (base PTX only — sm_100 target has no tcgen05)
// ---------------------------------------------------------------------------
__device__ __forceinline__ uint32_t f2tf32(float v) {
    uint32_t r; asm("cvt.rna.tf32.f32 %0, %1;" : "=r"(r) : "f"(v)); return r;
}
__device__ __forceinline__ float rna_f(float v) { return __uint_as_float(f2tf32(v)); }

__device__ __forceinline__ void cp_async16(uint32_t dst, const void* src) {
    asm volatile("cp.async.cg.shared.global [%0], [%1], 16;\n" :: "r"(dst), "l"(src));
}
__device__ __forceinline__ void cp_async16b(uint32_t dst, const void* src, int bytes) {
    asm volatile("cp.async.cg.shared.global [%0], [%1], 16, %2;\n" :: "r"(dst), "l"(src), "r"(bytes));
}
__device__ __forceinline__ void cp_async4(uint32_t dst, const void* src, int bytes) {
    asm volatile("cp.async.ca.shared.global [%0], [%1], 4, %2;\n" :: "r"(dst), "l"(src), "r"(bytes));
}
__device__ __forceinline__ void cp_commit() {
    asm volatile("cp.async.commit_group;\n" ::: "memory");
}
#define CP_WAIT(n) asm volatile("cp.async.wait_group %0;\n" :: "n"(n) : "memory")

__device__ __forceinline__ void mma_tf32(float* d, const uint32_t* a, const uint32_t* b) {
    asm volatile(
        "mma.sync.aligned.m16n8k8.row.col.f32.tf32.tf32.f32 "
        "{%0,%1,%2,%3}, {%4,%5,%6,%7}, {%8,%9}, {%0,%1,%2,%3};"
        : "+f"(d[0]), "+f"(d[1]), "+f"(d[2]), "+f"(d[3])
        : "r"(a[0]), "r"(a[1]), "r"(a[2]), "r"(a[3]), "r"(b[0]), "r"(b[1]));
}

// ---------------------------------------------------------------------------
// GEMM2: h1 = relu(adj @ xw + b1)   [M=8192, N=1024, K=8192]
// CTA 128m x 256n, BK=32, 8 warps (2x4) of 64x64.
// 3-stage A (LDG->cvt->STS) + 3-stage B (cp.async), ONE sync per ktile,
// fragment double-buffering across the 4 k-groups.
// ---------------------------------------------------------------------------
constexpr int LDA_S = 36;
constexpr int LDB_S = 40;
constexpr int A_STG = 128 * LDA_S;             // 4608 floats
constexpr int B_STG = 256 * LDB_S;             // 10240 floats
constexpr int B_BASE = 3 * A_STG;              // floats
constexpr int G2_SMEM = (3 * A_STG + 3 * B_STG) * 4;   // 178176 B
constexpr int KT2 = NN / 32;                   // 256

__global__ __launch_bounds__(256, 1)
void gemm2_mma(const float* __restrict__ adj,
               const float* __restrict__ xwT,
               const float* __restrict__ bias,
               float* __restrict__ C)
{
    extern __shared__ float smf[];
    const uint32_t smb = (uint32_t)__cvta_generic_to_shared(smf);
    const int tid  = threadIdx.x;
    const int lane = tid & 31;
    const int wid  = tid >> 5;
    const int wm   = (wid & 1) * 64;
    const int wn   = (wid >> 1) * 64;
    const int r    = lane >> 2;
    const int c4   = lane & 3;
    const int m0   = blockIdx.y * 128;
    const int n0   = blockIdx.x * 256;

    const float* Abase = adj + (size_t)m0 * NN;
    const float* Bbase = xwT + (size_t)n0 * NN;

    float acc[4][8][4];
    #pragma unroll
    for (int i = 0; i < 4; i++)
        #pragma unroll
        for (int j = 0; j < 8; j++)
            #pragma unroll
            for (int q = 0; q < 4; q++) acc[i][j][q] = 0.f;

    float4 buf[4];

    auto ldgA = [&](int kt) {
        #pragma unroll
        for (int c = 0; c < 4; c++) {
            int chunk = tid + c * 256;
            int row = chunk >> 3, pos = chunk & 7;
            buf[c] = *(const float4*)(Abase + (size_t)row * NN + kt * 32 + pos * 4);
        }
    };
    auto stsA = [&](int s) {
        float* As = smf + s * A_STG;
        #pragma unroll
        for (int c = 0; c < 4; c++) {
            int chunk = tid + c * 256;
            int row = chunk >> 3, pos = chunk & 7;
            float4 v = buf[c];
            v.x = rna_f(v.x); v.y = rna_f(v.y); v.z = rna_f(v.z); v.w = rna_f(v.w);
            *(float4*)(As + row * LDA_S + pos * 4) = v;
        }
    };
    auto cpB = [&](int kt, int s) {
        uint32_t bs = smb + (uint32_t)(B_BASE + s * B_STG) * 4;
        const float* Bb = Bbase + kt * 32;
        #pragma unroll
        for (int c = 0; c < 8; c++) {
            int chunk = tid + c * 256;
            int row = chunk >> 3, pos = chunk & 7;
            cp_async16(bs + (uint32_t)(row * LDB_S + pos * 4) * 4,
                       Bb + (size_t)row * NN + pos * 4);
        }
        cp_commit();
    };

    // fragment buffers (double-buffered across k-groups)
    uint32_t a[2][4][4], b[2][8][2];

    auto load_frags = [&](const uint32_t* As, const float* Bf, int g, int p) {
        const int kk = g * 8;
        #pragma unroll
        for (int mi = 0; mi < 4; mi++) {
            int base = (wm + mi * 16 + r) * LDA_S + kk + c4;
            a[p][mi][0] = As[base];
            a[p][mi][1] = As[base + 8 * LDA_S];
            a[p][mi][2] = As[base + 4];
            a[p][mi][3] = As[base + 8 * LDA_S + 4];
        }
        #pragma unroll
        for (int ni = 0; ni < 8; ni++) {
            float2 v = *(const float2*)(Bf + (wn + ni * 8 + r) * LDB_S + kk + 2 * c4);
            b[p][ni][0] = __float_as_uint(v.x);
            b[p][ni][1] = __float_as_uint(v.y);
        }
    };

    // ---- prologue ----
    ldgA(0);
    cpB(0, 0);                 // group 0
    cpB(1, 1);                 // group 1
    stsA(0);                   // A stage 0 (kt=0)
    ldgA(1);                   // buf <- kt=1

    for (int kt = 0; kt < KT2; kt++) {
        // write A stage for kt+1 (stage last read at kt-2; previous barrier covers WAR)
        if (kt + 1 < KT2) stsA((kt + 1) % 3);

        // B group kt must be complete (last issued group is kt+1)
        if (kt + 1 < KT2) { CP_WAIT(1); } else { CP_WAIT(0); }
        __syncthreads();       // publishes A stage (kt+1)%3 and B stage kt%3

        // prefetch for kt+2 (B stage (kt+2)%3 == (kt-1)%3, readers done per the barrier)
        if (kt + 2 < KT2) { cpB(kt + 2, (kt + 2) % 3); ldgA(kt + 2); }

        const uint32_t* As = (const uint32_t*)(smf + (kt % 3) * A_STG);
        const float*    Bf = (const float*)(smf + B_BASE + (kt % 3) * B_STG);

        load_frags(As, Bf, 0, 0);
        #pragma unroll
        for (int g = 0; g < 4; g++) {
            if (g < 3) load_frags(As, Bf, g + 1, (g + 1) & 1);
            const int p = g & 1;
            #pragma unroll
            for (int mi = 0; mi < 4; mi++)
                #pragma unroll
                for (int ni = 0; ni < 8; ni++)
                    mma_tf32(acc[mi][ni], a[p][mi], b[p][ni]);
        }
    }

    // epilogue: bias + relu
    #pragma unroll
    for (int mi = 0; mi < 4; mi++) {
        #pragma unroll
        for (int h = 0; h < 2; h++) {
            int row = m0 + wm + mi * 16 + r + h * 8;
            float* dst = C + (size_t)row * HPAD + n0 + wn;
            #pragma unroll
            for (int ni = 0; ni < 8; ni++) {
                int col = ni * 8 + c4 * 2;
                float2 v;
                v.x = fmaxf(acc[mi][ni][h * 2 + 0] + bias[n0 + wn + col],     0.f);
                v.y = fmaxf(acc[mi][ni][h * 2 + 1] + bias[n0 + wn + col + 1], 0.f);
                *(float2*)(dst + col) = v;
            }
        }
    }
}

// ---------------------------------------------------------------------------
// GEMM1 (proven): xw = feat @ W1  [tf32 HMMA, K=343]
// ---------------------------------------------------------------------------
constexpr int BM = 128, BN = 128, BK = 32;
constexpr int LDAS = 36, LDBS = 136;
constexpr int A_SZ = BM * LDAS, B_SZ = BK * LDBS;
constexpr int STAGE = A_SZ + B_SZ;
constexpr int G1_SMEM = 2 * STAGE * 4;

__global__ __launch_bounds__(256, 1)
void gemm1_hmma(const float* __restrict__ A, const float* __restrict__ B,
                float* __restrict__ C, int M, int N, int K, int lda, int ldb, int ldc)
{
    extern __shared__ float sm[];
    const int tid = threadIdx.x, lane = tid & 31, wid = tid >> 5;
    const int wm0 = (wid & 1) * 64, wn0 = (wid >> 1) * 32;
    const int m0 = blockIdx.y * BM, n0 = blockIdx.x * BN;
    const uint32_t smbase = (uint32_t)__cvta_generic_to_shared(sm);

    float acc[4][4][4];
    #pragma unroll
    for (int i = 0; i < 4; i++)
        #pragma unroll
        for (int j = 0; j < 4; j++)
            #pragma unroll
            for (int q = 0; q < 4; q++) acc[i][j][q] = 0.f;

    auto loadA = [&](int kt, int s) {
        const int k0 = kt * BK;
        #pragma unroll
        for (int t = 0; t < 16; t++) {
            int id = tid + t * 256;
            int m = id >> 5, c = id & 31;
            int gk = k0 + c;
            int bytes = (gk < K) ? 4 : 0;
            const float* src = bytes ? (A + (size_t)(m0 + m) * lda + gk) : A;
            cp_async4(smbase + (uint32_t)(s * STAGE + m * LDAS + c) * 4, src, bytes);
        }
    };
    auto loadB = [&](int kt, int s) {
        const int k0 = kt * BK;
        #pragma unroll
        for (int t = 0; t < 4; t++) {
            int id = tid + t * 256;
            int k = id >> 5, c = id & 31;
            int gk = k0 + k, gn = n0 + c * 4;
            int bytes = 0;
            if (gk < K) { bytes = (N - gn) * 4; bytes = bytes < 0 ? 0 : (bytes > 16 ? 16 : bytes); }
            const float* src = bytes ? (B + (size_t)gk * ldb + gn) : B;
            cp_async16b(smbase + (uint32_t)(s * STAGE + A_SZ + k * LDBS + c * 4) * 4, src, bytes);
        }
    };

    const int KT = (K + BK - 1) / BK;
    const int r = lane >> 2, c4 = lane & 3;
    loadA(0, 0); loadB(0, 0); cp_commit();

    for (int kt = 0; kt < KT; kt++) {
        if (kt + 1 < KT) {
            loadA(kt + 1, (kt + 1) & 1);
            loadB(kt + 1, (kt + 1) & 1);
            cp_commit();
            CP_WAIT(1);
        } else {
            CP_WAIT(0);
        }
        __syncthreads();
        const float* As  = sm + (kt & 1) * STAGE;
        const float* Bsm = As + A_SZ;
        #pragma unroll
        for (int kk4 = 0; kk4 < 4; kk4++) {
            const int kk = kk4 * 8;
            uint32_t a[4][4], b[4][2];
            #pragma unroll
            for (int mi = 0; mi < 4; mi++) {
                int base = (wm0 + mi * 16 + r) * LDAS + kk + c4;
                a[mi][0] = f2tf32(As[base]);
                a[mi][1] = f2tf32(As[base + 8 * LDAS]);
                a[mi][2] = f2tf32(As[base + 4]);
                a[mi][3] = f2tf32(As[base + 8 * LDAS + 4]);
            }
            #pragma unroll
            for (int ni = 0; ni < 4; ni++) {
                int bb = (kk + c4) * LDBS + wn0 + ni * 8 + r;
                b[ni][0] = f2tf32(Bsm[bb]);
                b[ni][1] = f2tf32(Bsm[bb + 4 * LDBS]);
            }
            #pragma unroll
            for (int mi = 0; mi < 4; mi++)
                #pragma unroll
                for (int ni = 0; ni < 4; ni++)
                    mma_tf32(acc[mi][ni], a[mi], b[ni]);
        }
        __syncthreads();
    }

    #pragma unroll
    for (int mi = 0; mi < 4; mi++)
        #pragma unroll
        for (int ni = 0; ni < 4; ni++) {
            int row0 = m0 + wm0 + mi * 16 + r;
            int col0 = n0 + wn0 + ni * 8 + c4 * 2;
            #pragma unroll
            for (int h = 0; h < 2; h++) {
                int row = row0 + h * 8;
                #pragma unroll
                for (int q = 0; q < 2; q++) {
                    int col = col0 + q;
                    if (col < N) C[(size_t)row * ldc + col] = acc[mi][ni][h * 2 + q];
                }
            }
        }
}

// ---------------------------------------------------------------------------
// transpose + RNA round + k-permute: xw[8192][1024] -> xwT[1024][8192]
// ---------------------------------------------------------------------------
__global__ void transpose_rna_perm(const float* __restrict__ in,
                                   float* __restrict__ out)
{
    __shared__ float t[32][33];
    int x  = blockIdx.x * 32 + threadIdx.x;
    int y0 = blockIdx.y * 32;
    #pragma unroll
    for (int j = threadIdx.y; j < 32; j += 8)
        t[j][threadIdx.x] = in[(size_t)(y0 + j) * HPAD + x];
    __syncthreads();
    int k  = y0 + threadIdx.x;
    int o  = k & 7;
    int kp = (k & ~7) | ((o < 4) ? (2 * o) : (2 * (o - 4) + 1));
    int n0 = blockIdx.x * 32;
    #pragma unroll
    for (int j = threadIdx.y; j < 32; j += 8)
        out[(size_t)(n0 + j) * NN + kp] = rna_f(t[threadIdx.x][j]);
}

__global__ void pad_bias_kernel(const float* __restrict__ b1, float* __restrict__ b1p) {
    int i = threadIdx.x;
    b1p[i] = (i < HIDD) ? b1[i] : 0.f;
}

// ---------------------------------------------------------------------------
// LayerNorm(1000) + head, one warp per row.
// ---------------------------------------------------------------------------
__global__ __launch_bounds__(256)
void ln_head_kernel(const float* __restrict__ h,
                    const float* __restrict__ gamma,
                    const float* __restrict__ beta,
                    const float* __restrict__ Wm,
                    const float* __restrict__ bm,
                    float* __restrict__ out)
{
    const int row  = blockIdx.x * 8 + threadIdx.y;
    if (row >= NN) return;
    const int lane = threadIdx.x;
    const float* hr = h + (size_t)row * HPAD;

    float v[32];
    float s = 0.f, ss = 0.f;
    #pragma unroll
    for (int i = 0; i < 32; i++) {
        int n = lane + 32 * i;
        float x = (n < HIDD) ? hr[n] : 0.f;
        v[i] = x; s += x; ss += x * x;
    }
    #pragma unroll
    for (int off = 16; off > 0; off >>= 1) {
        s  += __shfl_xor_sync(0xFFFFFFFF, s,  off);
        ss += __shfl_xor_sync(0xFFFFFFFF, ss, off);
    }
    const float mu   = s * (1.0f / HIDD);
    const float var  = ss * (1.0f / HIDD) - mu * mu;
    const float rinv = rsqrtf(var + EPS);

    float acc[OUTD] = {0.f, 0.f, 0.f, 0.f};
    #pragma unroll
    for (int i = 0; i < 32; i++) {
        int n = lane + 32 * i;
        if (n < HIDD) {
            float xn = (v[i] - mu) * rinv * gamma[n] + beta[n];
            #pragma unroll
            for (int o = 0; o < OUTD; o++)
                acc[o] = fmaf(xn, Wm[n * OUTD + o], acc[o]);
        }
    }
    #pragma unroll
    for (int o = 0; o < OUTD; o++) {
        #pragma unroll
        for (int off = 16; off > 0; off >>= 1)
            acc[o] += __shfl_xor_sync(0xFFFFFFFF, acc[o], off);
    }
    if (lane == 0) {
        #pragma unroll
        for (int o = 0; o < OUTD; o++)
            out[(size_t)row * OUTD + o] = acc[o] + bm[o];
    }
}

// ---------------------------------------------------------------------------
extern "C" void kernel_launch(void* const* d_in, const int* in_sizes, int n_in,
                              void* d_out, int out_size)
{
    const float* adj   = (const float*)d_in[0];
    const float* feat  = (const float*)d_in[1];
    const float* W1    = (const float*)d_in[2];
    const float* b1    = (const float*)d_in[3];
    const float* gamma = (const float*)d_in[4];
    const float* beta  = (const float*)d_in[5];
    const float* Wm    = (const float*)d_in[6];
    const float* bm    = (const float*)d_in[7];
    float* out = (float*)d_out;

    float *xw, *xwT, *h1, *b1p;
    cudaGetSymbolAddress((void**)&xw,  g_xw);
    cudaGetSymbolAddress((void**)&xwT, g_xwT);
    cudaGetSymbolAddress((void**)&h1,  g_h1);
    cudaGetSymbolAddress((void**)&b1p, g_b1p);

    cudaFuncSetAttribute(gemm1_hmma, cudaFuncAttributeMaxDynamicSharedMemorySize, G1_SMEM);
    cudaFuncSetAttribute(gemm2_mma,  cudaFuncAttributeMaxDynamicSharedMemorySize, G2_SMEM);

    cudaMemsetAsync(xw, 0, (size_t)NN * HPAD * sizeof(float));
    pad_bias_kernel<<<1, HPAD>>>(b1, b1p);

    // GEMM1: xw = feat @ W1
    {
        dim3 grid((HIDD + BN - 1) / BN, NN / BM);
        gemm1_hmma<<<grid, 256, G1_SMEM>>>(feat, W1, xw, NN, HIDD, IND, IND, HIDD, HPAD);
    }

    // xwT = RNA(xw)^T with k-permute
    {
        dim3 block(32, 8), grid(HPAD / 32, NN / 32);
        transpose_rna_perm<<<grid, block>>>(xw, xwT);
    }

    // GEMM2: h1 = relu(adj @ xw + b1)
    {
        dim3 grid(HPAD / 256, NN / 128);
        gemm2_mma<<<grid, 256, G2_SMEM>>>(adj, xwT, b1p, h1);
    }

    // LayerNorm + head
    {
        dim3 block(32, 8);
        ln_head_kernel<<<NN / 8, block>>>(h1, gamma, beta, Wm, bm, out);
    }
}